// round 9
// baseline (speedup 1.0000x reference)
#include <cuda_runtime.h>
#include <cuda_bf16.h>
#include <cstdint>

// ---------------------------------------------------------------------------
// AggrEGATConv fused EGAT convolution.
//   output: res_n [N,16] followed by res_e [E,16], f32
// ---------------------------------------------------------------------------

#define MAXN 100000
#define MAXE 1600000

__device__ float g_fni [(size_t)MAXN * 64];
__device__ float g_fnj [(size_t)MAXN * 64];
__device__ float g_hsrc[(size_t)MAXN * 64];
__device__ float g_ex  [(size_t)MAXE * 4];
__device__ float g_z   [(size_t)MAXN * 4];
// W_fij bf16 hi/lo, transposed, fragment-paired:
//   g_wp[n*32 + kt*8 + 2q + {0,1}] = hi:(w[8kt+q], w[8kt+4+q]) as 2 u32 words
//   (hi plane then lo plane)
__device__ unsigned g_wph[64 * 32];
__device__ unsigned g_wpl[64 * 32];

// ---- helpers ---------------------------------------------------------------
__device__ __forceinline__ unsigned long long pack2(float x, float y) {
    unsigned long long r;
    asm("mov.b64 %0, {%1, %2};"
        : "=l"(r) : "r"(__float_as_uint(x)), "r"(__float_as_uint(y)));
    return r;
}
__device__ __forceinline__ unsigned long long ffma2(unsigned long long a,
                                                    unsigned long long b,
                                                    unsigned long long c) {
    unsigned long long d;
    asm("fma.rn.f32x2 %0, %1, %2, %3;" : "=l"(d) : "l"(a), "l"(b), "l"(c));
    return d;
}
__device__ __forceinline__ void red_add_v4(float* p, float a, float b,
                                           float c, float d) {
    asm volatile("red.global.add.v4.f32 [%0], {%1, %2, %3, %4};"
                 :: "l"(p), "f"(a), "f"(b), "f"(c), "f"(d) : "memory");
}
__device__ __forceinline__ unsigned bf16pack(float lo_elem, float hi_elem) {
    unsigned short ulo = __bfloat16_as_ushort(__float2bfloat16(lo_elem));
    unsigned short uhi = __bfloat16_as_ushort(__float2bfloat16(hi_elem));
    return (unsigned)ulo | ((unsigned)uhi << 16);
}
__device__ __forceinline__ float bf16residual(float x) {
    return x - __bfloat162float(__float2bfloat16(x));
}
__device__ __forceinline__ void mma16816(float& d0, float& d1, float& d2,
                                         float& d3, unsigned a0, unsigned a1,
                                         unsigned a2, unsigned a3,
                                         unsigned b0, unsigned b1) {
    asm volatile(
        "mma.sync.aligned.m16n8k16.row.col.f32.bf16.bf16.f32 "
        "{%0,%1,%2,%3}, {%4,%5,%6,%7}, {%8,%9}, {%0,%1,%2,%3};"
        : "+f"(d0), "+f"(d1), "+f"(d2), "+f"(d3)
        : "r"(a0), "r"(a1), "r"(a2), "r"(a3), "r"(b0), "r"(b1));
}

// edge_main strides (words)
#define XS     36        // x rows: 36 mod 32 == 4 -> conflict-free scalar frags
#define WREG   1152      // per-warp x region (hi+lo), 16*36*2
#define WPS    34        // W uint2-paired rows: (2g + 8q) distinct per phase
// smem total: 2*64*WPS + 8*WREG + 128 words = 13568 words = 54272 B -> 4 blk/SM

// ---------------------------------------------------------------------------
// Kernel 0: zero res_n and z.
// ---------------------------------------------------------------------------
__global__ void zero_kernel(float* __restrict__ out_n, int N) {
    int i = blockIdx.x * 256 + threadIdx.x;
    if (i < N * 16) out_n[i] = 0.0f;
    if (i < N * 4)  g_z[i]   = 0.0f;
}

// ---------------------------------------------------------------------------
// Kernel W: split W_fij into bf16 hi/lo transposed fragment-PAIRED words.
//   j enumerates (n, kt, q, h) with h = pair half {0: w[8kt+q], 1: w[8kt+4+q]}
// ---------------------------------------------------------------------------
__global__ void wsplit(const float* __restrict__ Wfij) {
    int j = blockIdx.x * 256 + threadIdx.x;   // 0..2047
    if (j >= 2048) return;
    int n  = j >> 5;            // 0..63 (output col)
    int r  = j & 31;
    int kt = r >> 3;            // 0..3
    int q  = (r >> 1) & 3;      // 0..3
    int h  = r & 1;             // pair half
    int kp = kt * 8 + q + h * 4;     // k-pair index 0..31
    float w0 = Wfij[(2 * kp) * 64 + n];
    float w1 = Wfij[(2 * kp + 1) * 64 + n];
    int idx = n * WPS + kt * 8 + q * 2 + h;
    g_wph[idx - n * (WPS - 32)] = 0;  // dummy guard removed below
    // store directly in padded layout positions via separate arrays:
    // (we store unpadded in global; smem staging applies the pad)
    g_wph[j] = bf16pack(w0, w1);
    g_wpl[j] = bf16pack(bf16residual(w0), bf16residual(w1));
}

// ---------------------------------------------------------------------------
// Kernel 1: node GEMMs (FFMA2, R7-proven).  One thread = one node.
// ---------------------------------------------------------------------------
__global__ __launch_bounds__(256)
void node_gemm(const float* __restrict__ nf,
               const float* __restrict__ Wni,
               const float* __restrict__ Wnj,
               const float* __restrict__ Wsrc,
               const float* __restrict__ bsrc,
               int N)
{
    __shared__ ulonglong2 sW[128 * 16];
    __shared__ float      sb[64];

    const int which = blockIdx.y;
    const float* W = (which == 0) ? Wni : (which == 1) ? Wnj : Wsrc;
    float* out = (which == 0) ? g_fni : (which == 1) ? g_fnj : g_hsrc;

    const float4* Wv = (const float4*)W;
    for (int i = threadIdx.x; i < 2048; i += 256) {
        float4 w = Wv[i];
        ulonglong2 u;
        u.x = pack2(w.x, w.y);
        u.y = pack2(w.z, w.w);
        sW[i] = u;
    }
    if (threadIdx.x < 64)
        sb[threadIdx.x] = (which == 2) ? bsrc[threadIdx.x] : 0.0f;
    __syncthreads();

    const int n = blockIdx.x * 256 + threadIdx.x;
    if (n >= N) return;

    unsigned long long acc[32];
#pragma unroll
    for (int p = 0; p < 32; ++p) acc[p] = 0ull;

    const float4* xv = (const float4*)(nf + (size_t)n * 128);
#pragma unroll 4
    for (int k4 = 0; k4 < 32; ++k4) {
        float4 xq = xv[k4];
#pragma unroll
        for (int j = 0; j < 4; ++j) {
            float xs = (j == 0) ? xq.x : (j == 1) ? xq.y : (j == 2) ? xq.z : xq.w;
            unsigned long long xx = pack2(xs, xs);
            const int k = k4 * 4 + j;
#pragma unroll
            for (int q = 0; q < 16; ++q) {
                ulonglong2 w = sW[k * 16 + q];
                acc[2 * q]     = ffma2(xx, w.x, acc[2 * q]);
                acc[2 * q + 1] = ffma2(xx, w.y, acc[2 * q + 1]);
            }
        }
    }

    float* o = out + (size_t)n * 64;
#pragma unroll
    for (int p = 0; p < 32; ++p) {
        float2 v = *(float2*)&acc[p];
        o[2 * p]     = v.x + sb[2 * p];
        o[2 * p + 1] = v.y + sb[2 * p + 1];
    }
}

// ---------------------------------------------------------------------------
// Kernel 2: edge pass 1 via tensor cores (bf16x3) with uint2 B-frag loads.
// ---------------------------------------------------------------------------
__global__ __launch_bounds__(256, 4)
void edge_main(const float* __restrict__ efeats,
               const int*   __restrict__ src,
               const int*   __restrict__ dst,
               const float* __restrict__ attn,
               const float* __restrict__ bias_e,
               float* __restrict__ out_e,
               int E)
{
    extern __shared__ char dyns[];
    unsigned* s_wh = (unsigned*)dyns;                    // 64*WPS u32
    unsigned* s_wl = s_wh + 64 * WPS;
    unsigned* s_x  = s_wl + 64 * WPS;                    // 8 * WREG u32
    float*    s_attn = (float*)(s_x + 8 * WREG);
    float*    s_bias = s_attn + 64;

    const int tid  = threadIdx.x;
    const int lane = tid & 31;
    const int w    = tid >> 5;

    // stage W paired-frag words into padded rows (stride WPS=34)
    for (int j = tid; j < 2048; j += 256) {
        int n = j >> 5, r = j & 31;
        s_wh[n * WPS + r] = g_wph[j];
        s_wl[n * WPS + r] = g_wpl[j];
    }
    if (tid < 64) {
        s_attn[tid] = attn[tid];
        s_bias[tid] = bias_e[tid];
    }

    const long long eblk = (long long)blockIdx.x * 128;
    {
        const float4* ef4 = (const float4*)efeats;
#pragma unroll
        for (int i = 0; i < 8; ++i) {
            int idx = i * 256 + tid;
            int e  = idx >> 4;
            int ch = idx & 15;
            float4 v = make_float4(0.f, 0.f, 0.f, 0.f);
            if (eblk + e < E) v = ef4[(eblk + e) * 16 + ch];
            unsigned h0 = bf16pack(v.x, v.y);
            unsigned h1 = bf16pack(v.z, v.w);
            unsigned l0 = bf16pack(bf16residual(v.x), bf16residual(v.y));
            unsigned l1 = bf16pack(bf16residual(v.z), bf16residual(v.w));
            unsigned* base = s_x + (e >> 4) * WREG + (e & 15) * XS + ch * 2;
            *(uint2*)(base)            = make_uint2(h0, h1);
            *(uint2*)(base + 16 * XS)  = make_uint2(l0, l1);
        }
    }
    __syncthreads();

    const long long ewarp = eblk + w * 16;
    const int g = lane >> 2;
    const int q = lane & 3;

    int myS = 0, myD = 0;
    if (lane < 16 && ewarp + lane < E) {
        myS = src[ewarp + lane];
        myD = dst[ewarp + lane];
    }

    float acc[8][4];
#pragma unroll
    for (int nt = 0; nt < 8; ++nt)
#pragma unroll
        for (int i = 0; i < 4; ++i) acc[nt][i] = 0.0f;

    const unsigned* xh0 = s_x + w * WREG + g * XS;
    const unsigned* xh8 = xh0 + 8 * XS;
    const unsigned* xl0 = xh0 + 16 * XS;
    const unsigned* xl8 = xl0 + 8 * XS;

#pragma unroll
    for (int kt = 0; kt < 4; ++kt) {
        const int kp = kt * 8 + q;
        unsigned ah0 = xh0[kp],     ah1 = xh8[kp];
        unsigned ah2 = xh0[kp + 4], ah3 = xh8[kp + 4];
        unsigned al0 = xl0[kp],     al1 = xl8[kp];
        unsigned al2 = xl0[kp + 4], al3 = xl8[kp + 4];
        const int woff = kt * 8 + q * 2;
#pragma unroll
        for (int nt = 0; nt < 8; ++nt) {
            uint2 bh = *(const uint2*)(s_wh + (nt * 8 + g) * WPS + woff);
            uint2 bl = *(const uint2*)(s_wl + (nt * 8 + g) * WPS + woff);
            mma16816(acc[nt][0], acc[nt][1], acc[nt][2], acc[nt][3],
                     ah0, ah1, ah2, ah3, bh.x, bh.y);
            mma16816(acc[nt][0], acc[nt][1], acc[nt][2], acc[nt][3],
                     ah0, ah1, ah2, ah3, bl.x, bl.y);
            mma16816(acc[nt][0], acc[nt][1], acc[nt][2], acc[nt][3],
                     al0, al1, al2, al3, bh.x, bh.y);
        }
    }
    __syncwarp();

    float* epiw = (float*)(s_x + w * WREG);
#pragma unroll
    for (int nt = 0; nt < 8; ++nt) {
        const int c = nt * 8 + 2 * q;
        *(float2*)(epiw + g * 66 + c)       = make_float2(acc[nt][0], acc[nt][1]);
        *(float2*)(epiw + (g + 8) * 66 + c) = make_float2(acc[nt][2], acc[nt][3]);
    }
    __syncwarp();

    const float b0 = s_bias[2 * lane];
    const float b1 = s_bias[2 * lane + 1];
    const float a0 = s_attn[2 * lane];
    const float a1 = s_attn[2 * lane + 1];

    for (int r = 0; r < 16; ++r) {
        long long e_r = ewarp + r;
        if (e_r >= E) break;
        const int s_r = __shfl_sync(0xffffffffu, myS, r);
        const int d_r = __shfl_sync(0xffffffffu, myD, r);

        float2 fa = *(const float2*)(g_fni + (size_t)s_r * 64 + 2 * lane);
        float2 fb = *(const float2*)(g_fnj + (size_t)d_r * 64 + 2 * lane);
        float2 ac = *(const float2*)(epiw + r * 66 + 2 * lane);

        float y0 = ac.x + fa.x + fb.x + b0;
        float y1 = ac.y + fa.y + fb.y + b1;
        y0 = (y0 > 0.0f) ? y0 : 0.01f * y0;
        y1 = (y1 > 0.0f) ? y1 : 0.01f * y1;

        float lp = y0 * a0 + y1 * a1;
        lp += __shfl_xor_sync(0xffffffffu, lp, 4);
        lp += __shfl_xor_sync(0xffffffffu, lp, 2);
        lp += __shfl_xor_sync(0xffffffffu, lp, 1);

        y0 += __shfl_xor_sync(0xffffffffu, y0, 8);
        y0 += __shfl_xor_sync(0xffffffffu, y0, 16);
        y1 += __shfl_xor_sync(0xffffffffu, y1, 8);
        y1 += __shfl_xor_sync(0xffffffffu, y1, 16);

        float l1v = __shfl_sync(0xffffffffu, lp, 8);
        float l2v = __shfl_sync(0xffffffffu, lp, 16);
        float l3v = __shfl_sync(0xffffffffu, lp, 24);

        if (lane < 8)
            *(float2*)(out_e + (size_t)e_r * 16 + 2 * lane) =
                make_float2(0.25f * y0, 0.25f * y1);

        if (lane == 0) {
            float e0 = expf(lp),  e1 = expf(l1v);
            float e2 = expf(l2v), e3 = expf(l3v);
            *(float4*)(g_ex + (size_t)e_r * 4) = make_float4(e0, e1, e2, e3);
            red_add_v4(&g_z[(size_t)d_r * 4], e0, e1, e2, e3);
        }
    }
}

// ---------------------------------------------------------------------------
// Kernel 3: invert z once per (node, head)
// ---------------------------------------------------------------------------
__global__ void inv_z(int N) {
    int i = blockIdx.x * 256 + threadIdx.x;
    if (i < N * 4) g_z[i] = __frcp_rn(g_z[i]);
}

// ---------------------------------------------------------------------------
// Kernel 4: edge pass 2.  4 lanes/edge; lane t owns dims 4t..4t+3; v4 RED.
// ---------------------------------------------------------------------------
__global__ __launch_bounds__(256)
void edge_aggr(const int* __restrict__ src,
               const int* __restrict__ dst,
               float* __restrict__ out_n,
               int E)
{
    const int tid  = threadIdx.x;
    const int lane = tid & 31;
    const int t    = lane & 3;
    const int le   = (tid >> 5) * 8 + (lane >> 2);
    const long long e = (long long)blockIdx.x * 64 + le;
    if (e >= E) return;

    const int s = src[e];
    const int d = dst[e];

    float4 ex4 = *(const float4*)(g_ex + (size_t)e * 4);
    float4 zi4 = *(const float4*)(g_z  + (size_t)d * 4);
    const float a0 = 0.25f * ex4.x * zi4.x;
    const float a1 = 0.25f * ex4.y * zi4.y;
    const float a2 = 0.25f * ex4.z * zi4.z;
    const float a3 = 0.25f * ex4.w * zi4.w;

    const float* hr = g_hsrc + (size_t)s * 64 + 4 * t;
    float4 v0 = *(const float4*)(hr);
    float4 v1 = *(const float4*)(hr + 16);
    float4 v2 = *(const float4*)(hr + 32);
    float4 v3 = *(const float4*)(hr + 48);

    float m0 = a0 * v0.x + a1 * v1.x + a2 * v2.x + a3 * v3.x;
    float m1 = a0 * v0.y + a1 * v1.y + a2 * v2.y + a3 * v3.y;
    float m2 = a0 * v0.z + a1 * v1.z + a2 * v2.z + a3 * v3.z;
    float m3 = a0 * v0.w + a1 * v1.w + a2 * v2.w + a3 * v3.w;

    red_add_v4(out_n + (size_t)d * 16 + 4 * t, m0, m1, m2, m3);
}

// ---------------------------------------------------------------------------
extern "C" void kernel_launch(void* const* d_in, const int* in_sizes, int n_in,
                              void* d_out, int out_size)
{
    const float* nfeats = (const float*)d_in[0];
    const float* efeats = (const float*)d_in[1];
    const int*   src    = (const int*)  d_in[2];
    const int*   dst    = (const int*)  d_in[3];
    const float* Wni    = (const float*)d_in[4];
    const float* Wnj    = (const float*)d_in[5];
    const float* Wfij   = (const float*)d_in[6];
    const float* Wsrc   = (const float*)d_in[7];
    const float* bsrc   = (const float*)d_in[8];
    const float* attn   = (const float*)d_in[9];
    const float* biase  = (const float*)d_in[10];

    const int N = in_sizes[0] / 128;
    const int E = in_sizes[2];

    float* out_n = (float*)d_out;
    float* out_e = out_n + (size_t)N * 16;

    static int smem_set = 0;
    const int EM_SMEM = (64 * WPS * 2 + 8 * WREG + 128) * 4;  // 54272 B
    if (!smem_set) {
        cudaFuncSetAttribute(edge_main,
                             cudaFuncAttributeMaxDynamicSharedMemorySize,
                             EM_SMEM);
        smem_set = 1;
    }

    // launch order: idx 3 (ncu's pick) = edge_main
    zero_kernel<<<(N * 16 + 255) / 256, 256>>>(out_n, N);

    wsplit<<<8, 256>>>(Wfij);

    dim3 g1((N + 255) / 256, 3);
    node_gemm<<<g1, 256>>>(nfeats, Wni, Wnj, Wsrc, bsrc, N);

    edge_main<<<(E + 127) / 128, 256, EM_SMEM>>>(efeats, src, dst,
                                                 attn, biase, out_e, E);

    inv_z<<<(N * 4 + 255) / 256, 256>>>(N);

    edge_aggr<<<(E + 63) / 64, 256>>>(src, dst, out_n, E);
}

// round 10
// speedup vs baseline: 1.3243x; 1.3243x over previous
#include <cuda_runtime.h>
#include <cuda_bf16.h>
#include <cstdint>

// ---------------------------------------------------------------------------
// AggrEGATConv fused EGAT convolution.
//   output: res_n [N,16] followed by res_e [E,16], f32
// ---------------------------------------------------------------------------

#define MAXN 100000
#define MAXE 1600000

__device__ float g_fni [(size_t)MAXN * 64];
__device__ float g_fnj [(size_t)MAXN * 64];
__device__ float g_hsrc[(size_t)MAXN * 64];
__device__ float g_ex  [(size_t)MAXE * 4];
__device__ float g_z   [(size_t)MAXN * 4];
// W_fij bf16 hi/lo, transposed (wt[n][kp]), packed (k,k+1) u32
__device__ unsigned g_wth[64 * 32];
__device__ unsigned g_wtl[64 * 32];

// ---- helpers ---------------------------------------------------------------
__device__ __forceinline__ unsigned long long pack2(float x, float y) {
    unsigned long long r;
    asm("mov.b64 %0, {%1, %2};"
        : "=l"(r) : "r"(__float_as_uint(x)), "r"(__float_as_uint(y)));
    return r;
}
__device__ __forceinline__ unsigned long long ffma2(unsigned long long a,
                                                    unsigned long long b,
                                                    unsigned long long c) {
    unsigned long long d;
    asm("fma.rn.f32x2 %0, %1, %2, %3;" : "=l"(d) : "l"(a), "l"(b), "l"(c));
    return d;
}
__device__ __forceinline__ void red_add_v4(float* p, float a, float b,
                                           float c, float d) {
    asm volatile("red.global.add.v4.f32 [%0], {%1, %2, %3, %4};"
                 :: "l"(p), "f"(a), "f"(b), "f"(c), "f"(d) : "memory");
}
__device__ __forceinline__ unsigned bf16pack(float lo_elem, float hi_elem) {
    unsigned short ulo = __bfloat16_as_ushort(__float2bfloat16(lo_elem));
    unsigned short uhi = __bfloat16_as_ushort(__float2bfloat16(hi_elem));
    return (unsigned)ulo | ((unsigned)uhi << 16);
}
__device__ __forceinline__ float bf16residual(float x) {
    return x - __bfloat162float(__float2bfloat16(x));
}
__device__ __forceinline__ void mma16816(float& d0, float& d1, float& d2,
                                         float& d3, unsigned a0, unsigned a1,
                                         unsigned a2, unsigned a3,
                                         unsigned b0, unsigned b1) {
    asm volatile(
        "mma.sync.aligned.m16n8k16.row.col.f32.bf16.bf16.f32 "
        "{%0,%1,%2,%3}, {%4,%5,%6,%7}, {%8,%9}, {%0,%1,%2,%3};"
        : "+f"(d0), "+f"(d1), "+f"(d2), "+f"(d3)
        : "r"(a0), "r"(a1), "r"(a2), "r"(a3), "r"(b0), "r"(b1));
}

// edge_main strides (words): 36 mod 32 == 4 -> conflict-free; even -> aligned
#define XS     36
#define WS     36
#define WREG   1152      // per-warp x region (hi+lo): 16*36*2; epi uses 16*68
#define EPS    68        // epilogue row stride: div by 4 -> 16B-aligned LDS.128

// ---------------------------------------------------------------------------
// Kernel 0: zero res_n and z.
// ---------------------------------------------------------------------------
__global__ void zero_kernel(float* __restrict__ out_n, int N) {
    int i = blockIdx.x * 256 + threadIdx.x;
    if (i < N * 16) out_n[i] = 0.0f;
    if (i < N * 4)  g_z[i]   = 0.0f;
}

// ---------------------------------------------------------------------------
// Kernel W: split W_fij into bf16 hi/lo transposed fragment words (R7 layout).
// ---------------------------------------------------------------------------
__global__ void wsplit(const float* __restrict__ Wfij) {
    int j = blockIdx.x * 256 + threadIdx.x;   // 0..2047
    if (j >= 2048) return;
    int n  = j >> 5;
    int kp = j & 31;
    float w0 = Wfij[(2 * kp) * 64 + n];
    float w1 = Wfij[(2 * kp + 1) * 64 + n];
    g_wth[j] = bf16pack(w0, w1);
    g_wtl[j] = bf16pack(bf16residual(w0), bf16residual(w1));
}

// ---------------------------------------------------------------------------
// Kernel 1: node GEMMs (FFMA2, R7-proven).  One thread = one node.
// ---------------------------------------------------------------------------
__global__ __launch_bounds__(256)
void node_gemm(const float* __restrict__ nf,
               const float* __restrict__ Wni,
               const float* __restrict__ Wnj,
               const float* __restrict__ Wsrc,
               const float* __restrict__ bsrc,
               int N)
{
    __shared__ ulonglong2 sW[128 * 16];
    __shared__ float      sb[64];

    const int which = blockIdx.y;
    const float* W = (which == 0) ? Wni : (which == 1) ? Wnj : Wsrc;
    float* out = (which == 0) ? g_fni : (which == 1) ? g_fnj : g_hsrc;

    const float4* Wv = (const float4*)W;
    for (int i = threadIdx.x; i < 2048; i += 256) {
        float4 w = Wv[i];
        ulonglong2 u;
        u.x = pack2(w.x, w.y);
        u.y = pack2(w.z, w.w);
        sW[i] = u;
    }
    if (threadIdx.x < 64)
        sb[threadIdx.x] = (which == 2) ? bsrc[threadIdx.x] : 0.0f;
    __syncthreads();

    const int n = blockIdx.x * 256 + threadIdx.x;
    if (n >= N) return;

    unsigned long long acc[32];
#pragma unroll
    for (int p = 0; p < 32; ++p) acc[p] = 0ull;

    const float4* xv = (const float4*)(nf + (size_t)n * 128);
#pragma unroll 4
    for (int k4 = 0; k4 < 32; ++k4) {
        float4 xq = xv[k4];
#pragma unroll
        for (int j = 0; j < 4; ++j) {
            float xs = (j == 0) ? xq.x : (j == 1) ? xq.y : (j == 2) ? xq.z : xq.w;
            unsigned long long xx = pack2(xs, xs);
            const int k = k4 * 4 + j;
#pragma unroll
            for (int q = 0; q < 16; ++q) {
                ulonglong2 w = sW[k * 16 + q];
                acc[2 * q]     = ffma2(xx, w.x, acc[2 * q]);
                acc[2 * q + 1] = ffma2(xx, w.y, acc[2 * q + 1]);
            }
        }
    }

    float* o = out + (size_t)n * 64;
#pragma unroll
    for (int p = 0; p < 32; ++p) {
        float2 v = *(float2*)&acc[p];
        o[2 * p]     = v.x + sb[2 * p];
        o[2 * p + 1] = v.y + sb[2 * p + 1];
    }
}

// ---------------------------------------------------------------------------
// Kernel 2: edge pass 1 via tensor cores (bf16x3, R7 MMA core).
//   New epilogue: 2 edges per round, half-warp per edge, lane owns 4 cols.
// ---------------------------------------------------------------------------
__global__ __launch_bounds__(256, 4)
void edge_main(const float* __restrict__ efeats,
               const int*   __restrict__ src,
               const int*   __restrict__ dst,
               const float* __restrict__ attn,
               const float* __restrict__ bias_e,
               float* __restrict__ out_e,
               int E)
{
    extern __shared__ char dyns[];
    unsigned* s_wh = (unsigned*)dyns;                    // 64*WS u32
    unsigned* s_wl = s_wh + 64 * WS;
    unsigned* s_x  = s_wl + 64 * WS;                     // 8 * WREG u32
    float*    s_attn = (float*)(s_x + 8 * WREG);
    float*    s_bias = s_attn + 64;

    const int tid  = threadIdx.x;
    const int lane = tid & 31;
    const int w    = tid >> 5;

    for (int j = tid; j < 2048; j += 256) {
        int n = j >> 5, kp = j & 31;
        s_wh[n * WS + kp] = g_wth[j];
        s_wl[n * WS + kp] = g_wtl[j];
    }
    if (tid < 64) {
        s_attn[tid] = attn[tid];
        s_bias[tid] = bias_e[tid];
    }

    const long long eblk = (long long)blockIdx.x * 128;
    {
        const float4* ef4 = (const float4*)efeats;
#pragma unroll
        for (int i = 0; i < 8; ++i) {
            int idx = i * 256 + tid;
            int e  = idx >> 4;
            int ch = idx & 15;
            float4 v = make_float4(0.f, 0.f, 0.f, 0.f);
            if (eblk + e < E) v = ef4[(eblk + e) * 16 + ch];
            unsigned h0 = bf16pack(v.x, v.y);
            unsigned h1 = bf16pack(v.z, v.w);
            unsigned l0 = bf16pack(bf16residual(v.x), bf16residual(v.y));
            unsigned l1 = bf16pack(bf16residual(v.z), bf16residual(v.w));
            unsigned* base = s_x + (e >> 4) * WREG + (e & 15) * XS + ch * 2;
            *(uint2*)(base)            = make_uint2(h0, h1);
            *(uint2*)(base + 16 * XS)  = make_uint2(l0, l1);
        }
    }
    __syncthreads();

    const long long ewarp = eblk + w * 16;
    const int g = lane >> 2;
    const int q = lane & 3;

    int myS = 0, myD = 0;
    if (lane < 16 && ewarp + lane < E) {
        myS = src[ewarp + lane];
        myD = dst[ewarp + lane];
    }

    float acc[8][4];
#pragma unroll
    for (int nt = 0; nt < 8; ++nt)
#pragma unroll
        for (int i = 0; i < 4; ++i) acc[nt][i] = 0.0f;

    const unsigned* xh0 = s_x + w * WREG + g * XS;
    const unsigned* xh8 = xh0 + 8 * XS;
    const unsigned* xl0 = xh0 + 16 * XS;
    const unsigned* xl8 = xl0 + 8 * XS;

#pragma unroll
    for (int kt = 0; kt < 4; ++kt) {
        const int kp = kt * 8 + q;
        unsigned ah0 = xh0[kp],     ah1 = xh8[kp];
        unsigned ah2 = xh0[kp + 4], ah3 = xh8[kp + 4];
        unsigned al0 = xl0[kp],     al1 = xl8[kp];
        unsigned al2 = xl0[kp + 4], al3 = xl8[kp + 4];
#pragma unroll
        for (int nt = 0; nt < 8; ++nt) {
            const unsigned* wb  = s_wh + (nt * 8 + g) * WS + kp;
            const unsigned* wlb = s_wl + (nt * 8 + g) * WS + kp;
            unsigned bh0 = wb[0],  bh1 = wb[4];
            unsigned bl0 = wlb[0], bl1 = wlb[4];
            mma16816(acc[nt][0], acc[nt][1], acc[nt][2], acc[nt][3],
                     ah0, ah1, ah2, ah3, bh0, bh1);
            mma16816(acc[nt][0], acc[nt][1], acc[nt][2], acc[nt][3],
                     ah0, ah1, ah2, ah3, bl0, bl1);
            mma16816(acc[nt][0], acc[nt][1], acc[nt][2], acc[nt][3],
                     al0, al1, al2, al3, bh0, bh1);
        }
    }
    __syncwarp();

    // scatter fragments into own x region (aliased epi buffer, stride EPS=68)
    float* epiw = (float*)(s_x + w * WREG);
#pragma unroll
    for (int nt = 0; nt < 8; ++nt) {
        const int c = nt * 8 + 2 * q;
        *(float2*)(epiw + g * EPS + c)       = make_float2(acc[nt][0], acc[nt][1]);
        *(float2*)(epiw + (g + 8) * EPS + c) = make_float2(acc[nt][2], acc[nt][3]);
    }
    __syncwarp();

    // epilogue: 2 edges/round; half-warp per edge; lane owns cols 4hl..4hl+3
    const int half = lane >> 4;
    const int hl   = lane & 15;
    const float4 bias4 = *(const float4*)(s_bias + 4 * hl);
    const float4 attn4 = *(const float4*)(s_attn + 4 * hl);

#pragma unroll 2
    for (int r2 = 0; r2 < 8; ++r2) {
        const int row = 2 * r2 + half;
        const long long e_r = ewarp + row;
        if (ewarp + 2 * r2 >= E) break;              // warp-uniform
        const bool valid = (e_r < E);
        const int s_r = __shfl_sync(0xffffffffu, myS, row);
        const int d_r = __shfl_sync(0xffffffffu, myD, row);

        float4 fa = *(const float4*)(g_fni + (size_t)s_r * 64 + 4 * hl);
        float4 fb = *(const float4*)(g_fnj + (size_t)d_r * 64 + 4 * hl);
        float4 ac = *(const float4*)(epiw + row * EPS + 4 * hl);

        float y0 = ac.x + fa.x + fb.x + bias4.x;
        float y1 = ac.y + fa.y + fb.y + bias4.y;
        float y2 = ac.z + fa.z + fb.z + bias4.z;
        float y3 = ac.w + fa.w + fb.w + bias4.w;
        y0 = (y0 > 0.0f) ? y0 : 0.01f * y0;
        y1 = (y1 > 0.0f) ? y1 : 0.01f * y1;
        y2 = (y2 > 0.0f) ? y2 : 0.01f * y2;
        y3 = (y3 > 0.0f) ? y3 : 0.01f * y3;

        // per-head logit (head = hl>>2): reduce over hl&3
        float lp = y0 * attn4.x + y1 * attn4.y + y2 * attn4.z + y3 * attn4.w;
        lp += __shfl_xor_sync(0xffffffffu, lp, 1);
        lp += __shfl_xor_sync(0xffffffffu, lp, 2);

        // res_e head-mean: cols differ by 16 -> hl differs by 4
        y0 += __shfl_xor_sync(0xffffffffu, y0, 4);
        y0 += __shfl_xor_sync(0xffffffffu, y0, 8);
        y1 += __shfl_xor_sync(0xffffffffu, y1, 4);
        y1 += __shfl_xor_sync(0xffffffffu, y1, 8);
        y2 += __shfl_xor_sync(0xffffffffu, y2, 4);
        y2 += __shfl_xor_sync(0xffffffffu, y2, 8);
        y3 += __shfl_xor_sync(0xffffffffu, y3, 4);
        y3 += __shfl_xor_sync(0xffffffffu, y3, 8);

        if (valid && hl < 4)
            *(float4*)(out_e + (size_t)e_r * 16 + 4 * hl) =
                make_float4(0.25f * y0, 0.25f * y1, 0.25f * y2, 0.25f * y3);

        // gather 4 head logits of own half
        const int hb = lane & 16;
        float l0 = __shfl_sync(0xffffffffu, lp, hb + 0);
        float l1 = __shfl_sync(0xffffffffu, lp, hb + 4);
        float l2 = __shfl_sync(0xffffffffu, lp, hb + 8);
        float l3 = __shfl_sync(0xffffffffu, lp, hb + 12);
        if (valid && hl == 0) {
            float e0 = expf(l0), e1 = expf(l1), e2 = expf(l2), e3 = expf(l3);
            *(float4*)(g_ex + (size_t)e_r * 4) = make_float4(e0, e1, e2, e3);
            red_add_v4(&g_z[(size_t)d_r * 4], e0, e1, e2, e3);
        }
    }
}

// ---------------------------------------------------------------------------
// Kernel 3: invert z once per (node, head)
// ---------------------------------------------------------------------------
__global__ void inv_z(int N) {
    int i = blockIdx.x * 256 + threadIdx.x;
    if (i < N * 4) g_z[i] = __frcp_rn(g_z[i]);
}

// ---------------------------------------------------------------------------
// Kernel 4: edge pass 2.  4 lanes/edge; lane t owns dims 4t..4t+3; v4 RED.
// ---------------------------------------------------------------------------
__global__ __launch_bounds__(256)
void edge_aggr(const int* __restrict__ src,
               const int* __restrict__ dst,
               float* __restrict__ out_n,
               int E)
{
    const int tid  = threadIdx.x;
    const int lane = tid & 31;
    const int t    = lane & 3;
    const int le   = (tid >> 5) * 8 + (lane >> 2);
    const long long e = (long long)blockIdx.x * 64 + le;
    if (e >= E) return;

    const int s = src[e];
    const int d = dst[e];

    float4 ex4 = *(const float4*)(g_ex + (size_t)e * 4);
    float4 zi4 = *(const float4*)(g_z  + (size_t)d * 4);
    const float a0 = 0.25f * ex4.x * zi4.x;
    const float a1 = 0.25f * ex4.y * zi4.y;
    const float a2 = 0.25f * ex4.z * zi4.z;
    const float a3 = 0.25f * ex4.w * zi4.w;

    const float* hr = g_hsrc + (size_t)s * 64 + 4 * t;
    float4 v0 = *(const float4*)(hr);
    float4 v1 = *(const float4*)(hr + 16);
    float4 v2 = *(const float4*)(hr + 32);
    float4 v3 = *(const float4*)(hr + 48);

    float m0 = a0 * v0.x + a1 * v1.x + a2 * v2.x + a3 * v3.x;
    float m1 = a0 * v0.y + a1 * v1.y + a2 * v2.y + a3 * v3.y;
    float m2 = a0 * v0.z + a1 * v1.z + a2 * v2.z + a3 * v3.z;
    float m3 = a0 * v0.w + a1 * v1.w + a2 * v2.w + a3 * v3.w;

    red_add_v4(out_n + (size_t)d * 16 + 4 * t, m0, m1, m2, m3);
}

// ---------------------------------------------------------------------------
extern "C" void kernel_launch(void* const* d_in, const int* in_sizes, int n_in,
                              void* d_out, int out_size)
{
    const float* nfeats = (const float*)d_in[0];
    const float* efeats = (const float*)d_in[1];
    const int*   src    = (const int*)  d_in[2];
    const int*   dst    = (const int*)  d_in[3];
    const float* Wni    = (const float*)d_in[4];
    const float* Wnj    = (const float*)d_in[5];
    const float* Wfij   = (const float*)d_in[6];
    const float* Wsrc   = (const float*)d_in[7];
    const float* bsrc   = (const float*)d_in[8];
    const float* attn   = (const float*)d_in[9];
    const float* biase  = (const float*)d_in[10];

    const int N = in_sizes[0] / 128;
    const int E = in_sizes[2];

    float* out_n = (float*)d_out;
    float* out_e = out_n + (size_t)N * 16;

    static int smem_set = 0;
    const int EM_SMEM = (64 * WS * 2 + 8 * WREG + 128) * 4;  // 55808 B
    if (!smem_set) {
        cudaFuncSetAttribute(edge_main,
                             cudaFuncAttributeMaxDynamicSharedMemorySize,
                             EM_SMEM);
        smem_set = 1;
    }

    // launch order: idx 3 (ncu's pick) = edge_main
    zero_kernel<<<(N * 16 + 255) / 256, 256>>>(out_n, N);

    wsplit<<<8, 256>>>(Wfij);

    dim3 g1((N + 255) / 256, 3);
    node_gemm<<<g1, 256>>>(nfeats, Wni, Wnj, Wsrc, bsrc, N);

    edge_main<<<(E + 127) / 128, 256, EM_SMEM>>>(efeats, src, dst,
                                                 attn, biase, out_e, E);

    inv_z<<<(N * 4 + 255) / 256, 256>>>(N);

    edge_aggr<<<(E + 63) / 64, 256>>>(src, dst, out_n, E);
}

// round 11
// speedup vs baseline: 1.3270x; 1.0021x over previous
#include <cuda_runtime.h>
#include <cuda_bf16.h>
#include <cstdint>

// ---------------------------------------------------------------------------
// AggrEGATConv fused EGAT convolution.
//   output: res_n [N,16] followed by res_e [E,16], f32
// ---------------------------------------------------------------------------

#define MAXN 100000
#define MAXE 1600000

__device__ float g_fni [(size_t)MAXN * 64];
__device__ float g_fnj [(size_t)MAXN * 64];
__device__ float g_hsrc[(size_t)MAXN * 64];
__device__ float g_ex  [(size_t)MAXE * 4];
__device__ float g_z   [(size_t)MAXN * 4];
// W_fij bf16 hi/lo, transposed (wt[n][kp]), packed (k,k+1) u32
__device__ unsigned g_wth[64 * 32];
__device__ unsigned g_wtl[64 * 32];

// ---- helpers ---------------------------------------------------------------
__device__ __forceinline__ unsigned long long pack2(float x, float y) {
    unsigned long long r;
    asm("mov.b64 %0, {%1, %2};"
        : "=l"(r) : "r"(__float_as_uint(x)), "r"(__float_as_uint(y)));
    return r;
}
__device__ __forceinline__ unsigned long long ffma2(unsigned long long a,
                                                    unsigned long long b,
                                                    unsigned long long c) {
    unsigned long long d;
    asm("fma.rn.f32x2 %0, %1, %2, %3;" : "=l"(d) : "l"(a), "l"(b), "l"(c));
    return d;
}
__device__ __forceinline__ void red_add_v4(float* p, float a, float b,
                                           float c, float d) {
    asm volatile("red.global.add.v4.f32 [%0], {%1, %2, %3, %4};"
                 :: "l"(p), "f"(a), "f"(b), "f"(c), "f"(d) : "memory");
}
// split (v0, v1) into packed bf16x2 hi word + packed bf16x2 residual word.
// cvt.rn.bf16x2.f32 d, a, b  ->  d = { upper = bf16(a), lower = bf16(b) }.
// Layout: lower 16 bits = v0 (lower-k element), upper = v1.
__device__ __forceinline__ void bf16split2(float v0, float v1,
                                           unsigned& h, unsigned& l) {
    asm("cvt.rn.bf16x2.f32 %0, %1, %2;" : "=r"(h) : "f"(v1), "f"(v0));
    float f0 = __uint_as_float(h << 16);           // bf16(v0) as f32 (exact)
    float f1 = __uint_as_float(h & 0xffff0000u);   // bf16(v1) as f32 (exact)
    float r0 = v0 - f0;
    float r1 = v1 - f1;
    asm("cvt.rn.bf16x2.f32 %0, %1, %2;" : "=r"(l) : "f"(r1), "f"(r0));
}
__device__ __forceinline__ void mma16816(float& d0, float& d1, float& d2,
                                         float& d3, unsigned a0, unsigned a1,
                                         unsigned a2, unsigned a3,
                                         unsigned b0, unsigned b1) {
    asm volatile(
        "mma.sync.aligned.m16n8k16.row.col.f32.bf16.bf16.f32 "
        "{%0,%1,%2,%3}, {%4,%5,%6,%7}, {%8,%9}, {%0,%1,%2,%3};"
        : "+f"(d0), "+f"(d1), "+f"(d2), "+f"(d3)
        : "r"(a0), "r"(a1), "r"(a2), "r"(a3), "r"(b0), "r"(b1));
}

// edge_main strides (words): 36 mod 32 == 4 -> conflict-free; even -> aligned
#define XS     36
#define WS     36
#define WREG   1152      // per-warp x region (hi+lo): 16*36*2; epi uses 16*68
#define EPS    68        // epilogue row stride: div by 4 -> 16B-aligned LDS.128

// ---------------------------------------------------------------------------
// Kernel 0: zero res_n and z.
// ---------------------------------------------------------------------------
__global__ void zero_kernel(float* __restrict__ out_n, int N) {
    int i = blockIdx.x * 256 + threadIdx.x;
    if (i < N * 16) out_n[i] = 0.0f;
    if (i < N * 4)  g_z[i]   = 0.0f;
}

// ---------------------------------------------------------------------------
// Kernel W: split W_fij into bf16 hi/lo transposed fragment words.
// ---------------------------------------------------------------------------
__global__ void wsplit(const float* __restrict__ Wfij) {
    int j = blockIdx.x * 256 + threadIdx.x;   // 0..2047
    if (j >= 2048) return;
    int n  = j >> 5;
    int kp = j & 31;
    float w0 = Wfij[(2 * kp) * 64 + n];
    float w1 = Wfij[(2 * kp + 1) * 64 + n];
    unsigned h, l;
    bf16split2(w0, w1, h, l);
    g_wth[j] = h;
    g_wtl[j] = l;
}

// ---------------------------------------------------------------------------
// Kernel 1: node GEMMs (FFMA2, R7-proven).  One thread = one node.
// ---------------------------------------------------------------------------
__global__ __launch_bounds__(256)
void node_gemm(const float* __restrict__ nf,
               const float* __restrict__ Wni,
               const float* __restrict__ Wnj,
               const float* __restrict__ Wsrc,
               const float* __restrict__ bsrc,
               int N)
{
    __shared__ ulonglong2 sW[128 * 16];
    __shared__ float      sb[64];

    const int which = blockIdx.y;
    const float* W = (which == 0) ? Wni : (which == 1) ? Wnj : Wsrc;
    float* out = (which == 0) ? g_fni : (which == 1) ? g_fnj : g_hsrc;

    const float4* Wv = (const float4*)W;
    for (int i = threadIdx.x; i < 2048; i += 256) {
        float4 w = Wv[i];
        ulonglong2 u;
        u.x = pack2(w.x, w.y);
        u.y = pack2(w.z, w.w);
        sW[i] = u;
    }
    if (threadIdx.x < 64)
        sb[threadIdx.x] = (which == 2) ? bsrc[threadIdx.x] : 0.0f;
    __syncthreads();

    const int n = blockIdx.x * 256 + threadIdx.x;
    if (n >= N) return;

    unsigned long long acc[32];
#pragma unroll
    for (int p = 0; p < 32; ++p) acc[p] = 0ull;

    const float4* xv = (const float4*)(nf + (size_t)n * 128);
#pragma unroll 4
    for (int k4 = 0; k4 < 32; ++k4) {
        float4 xq = xv[k4];
#pragma unroll
        for (int j = 0; j < 4; ++j) {
            float xs = (j == 0) ? xq.x : (j == 1) ? xq.y : (j == 2) ? xq.z : xq.w;
            unsigned long long xx = pack2(xs, xs);
            const int k = k4 * 4 + j;
#pragma unroll
            for (int q = 0; q < 16; ++q) {
                ulonglong2 w = sW[k * 16 + q];
                acc[2 * q]     = ffma2(xx, w.x, acc[2 * q]);
                acc[2 * q + 1] = ffma2(xx, w.y, acc[2 * q + 1]);
            }
        }
    }

    float* o = out + (size_t)n * 64;
#pragma unroll
    for (int p = 0; p < 32; ++p) {
        float2 v = *(float2*)&acc[p];
        o[2 * p]     = v.x + sb[2 * p];
        o[2 * p + 1] = v.y + sb[2 * p + 1];
    }
}

// ---------------------------------------------------------------------------
// Kernel 2: edge pass 1 via tensor cores (bf16x3, R10 structure).
// ---------------------------------------------------------------------------
__global__ __launch_bounds__(256, 4)
void edge_main(const float* __restrict__ efeats,
               const int*   __restrict__ src,
               const int*   __restrict__ dst,
               const float* __restrict__ attn,
               const float* __restrict__ bias_e,
               float* __restrict__ out_e,
               int E)
{
    extern __shared__ char dyns[];
    unsigned* s_wh = (unsigned*)dyns;                    // 64*WS u32
    unsigned* s_wl = s_wh + 64 * WS;
    unsigned* s_x  = s_wl + 64 * WS;                     // 8 * WREG u32
    float*    s_attn = (float*)(s_x + 8 * WREG);
    float*    s_bias = s_attn + 64;

    const int tid  = threadIdx.x;
    const int lane = tid & 31;
    const int w    = tid >> 5;

    for (int j = tid; j < 2048; j += 256) {
        int n = j >> 5, kp = j & 31;
        s_wh[n * WS + kp] = g_wth[j];
        s_wl[n * WS + kp] = g_wtl[j];
    }
    if (tid < 64) {
        s_attn[tid] = attn[tid];
        s_bias[tid] = bias_e[tid];
    }

    const long long eblk = (long long)blockIdx.x * 128;
    {
        const float4* ef4 = (const float4*)efeats;
#pragma unroll
        for (int i = 0; i < 8; ++i) {
            int idx = i * 256 + tid;
            int e  = idx >> 4;
            int ch = idx & 15;
            float4 v = make_float4(0.f, 0.f, 0.f, 0.f);
            if (eblk + e < E) v = ef4[(eblk + e) * 16 + ch];
            unsigned h0, l0, h1, l1;
            bf16split2(v.x, v.y, h0, l0);
            bf16split2(v.z, v.w, h1, l1);
            unsigned* base = s_x + (e >> 4) * WREG + (e & 15) * XS + ch * 2;
            *(uint2*)(base)            = make_uint2(h0, h1);
            *(uint2*)(base + 16 * XS)  = make_uint2(l0, l1);
        }
    }
    __syncthreads();

    const long long ewarp = eblk + w * 16;
    const int g = lane >> 2;
    const int q = lane & 3;

    int myS = 0, myD = 0;
    if (lane < 16 && ewarp + lane < E) {
        myS = src[ewarp + lane];
        myD = dst[ewarp + lane];
    }

    float acc[8][4];
#pragma unroll
    for (int nt = 0; nt < 8; ++nt)
#pragma unroll
        for (int i = 0; i < 4; ++i) acc[nt][i] = 0.0f;

    const unsigned* xh0 = s_x + w * WREG + g * XS;
    const unsigned* xh8 = xh0 + 8 * XS;
    const unsigned* xl0 = xh0 + 16 * XS;
    const unsigned* xl8 = xl0 + 8 * XS;

#pragma unroll
    for (int kt = 0; kt < 4; ++kt) {
        const int kp = kt * 8 + q;
        unsigned ah0 = xh0[kp],     ah1 = xh8[kp];
        unsigned ah2 = xh0[kp + 4], ah3 = xh8[kp + 4];
        unsigned al0 = xl0[kp],     al1 = xl8[kp];
        unsigned al2 = xl0[kp + 4], al3 = xl8[kp + 4];
#pragma unroll
        for (int nt = 0; nt < 8; ++nt) {
            const unsigned* wb  = s_wh + (nt * 8 + g) * WS + kp;
            const unsigned* wlb = s_wl + (nt * 8 + g) * WS + kp;
            unsigned bh0 = wb[0],  bh1 = wb[4];
            unsigned bl0 = wlb[0], bl1 = wlb[4];
            mma16816(acc[nt][0], acc[nt][1], acc[nt][2], acc[nt][3],
                     ah0, ah1, ah2, ah3, bh0, bh1);
            mma16816(acc[nt][0], acc[nt][1], acc[nt][2], acc[nt][3],
                     ah0, ah1, ah2, ah3, bl0, bl1);
            mma16816(acc[nt][0], acc[nt][1], acc[nt][2], acc[nt][3],
                     al0, al1, al2, al3, bh0, bh1);
        }
    }
    __syncwarp();

    // scatter fragments into own x region (aliased epi buffer, stride EPS=68)
    float* epiw = (float*)(s_x + w * WREG);
#pragma unroll
    for (int nt = 0; nt < 8; ++nt) {
        const int c = nt * 8 + 2 * q;
        *(float2*)(epiw + g * EPS + c)       = make_float2(acc[nt][0], acc[nt][1]);
        *(float2*)(epiw + (g + 8) * EPS + c) = make_float2(acc[nt][2], acc[nt][3]);
    }
    __syncwarp();

    // epilogue: 2 edges/round; half-warp per edge; lane owns cols 4hl..4hl+3
    const int half = lane >> 4;
    const int hl   = lane & 15;
    const float4 bias4 = *(const float4*)(s_bias + 4 * hl);
    const float4 attn4 = *(const float4*)(s_attn + 4 * hl);

#pragma unroll 2
    for (int r2 = 0; r2 < 8; ++r2) {
        const int row = 2 * r2 + half;
        const long long e_r = ewarp + row;
        if (ewarp + 2 * r2 >= E) break;              // warp-uniform
        const bool valid = (e_r < E);
        const int s_r = __shfl_sync(0xffffffffu, myS, row);
        const int d_r = __shfl_sync(0xffffffffu, myD, row);

        float4 fa = *(const float4*)(g_fni + (size_t)s_r * 64 + 4 * hl);
        float4 fb = *(const float4*)(g_fnj + (size_t)d_r * 64 + 4 * hl);
        float4 ac = *(const float4*)(epiw + row * EPS + 4 * hl);

        float y0 = ac.x + fa.x + fb.x + bias4.x;
        float y1 = ac.y + fa.y + fb.y + bias4.y;
        float y2 = ac.z + fa.z + fb.z + bias4.z;
        float y3 = ac.w + fa.w + fb.w + bias4.w;
        y0 = (y0 > 0.0f) ? y0 : 0.01f * y0;
        y1 = (y1 > 0.0f) ? y1 : 0.01f * y1;
        y2 = (y2 > 0.0f) ? y2 : 0.01f * y2;
        y3 = (y3 > 0.0f) ? y3 : 0.01f * y3;

        // per-head logit (head = hl>>2): reduce over hl&3
        float lp = y0 * attn4.x + y1 * attn4.y + y2 * attn4.z + y3 * attn4.w;
        lp += __shfl_xor_sync(0xffffffffu, lp, 1);
        lp += __shfl_xor_sync(0xffffffffu, lp, 2);

        // res_e head-mean: cols differ by 16 -> hl differs by 4
        y0 += __shfl_xor_sync(0xffffffffu, y0, 4);
        y0 += __shfl_xor_sync(0xffffffffu, y0, 8);
        y1 += __shfl_xor_sync(0xffffffffu, y1, 4);
        y1 += __shfl_xor_sync(0xffffffffu, y1, 8);
        y2 += __shfl_xor_sync(0xffffffffu, y2, 4);
        y2 += __shfl_xor_sync(0xffffffffu, y2, 8);
        y3 += __shfl_xor_sync(0xffffffffu, y3, 4);
        y3 += __shfl_xor_sync(0xffffffffu, y3, 8);

        if (valid && hl < 4)
            *(float4*)(out_e + (size_t)e_r * 16 + 4 * hl) =
                make_float4(0.25f * y0, 0.25f * y1, 0.25f * y2, 0.25f * y3);

        // gather 4 head logits of own half
        const int hb = lane & 16;
        float l0 = __shfl_sync(0xffffffffu, lp, hb + 0);
        float l1 = __shfl_sync(0xffffffffu, lp, hb + 4);
        float l2 = __shfl_sync(0xffffffffu, lp, hb + 8);
        float l3 = __shfl_sync(0xffffffffu, lp, hb + 12);
        if (valid && hl == 0) {
            float e0 = expf(l0), e1 = expf(l1), e2 = expf(l2), e3 = expf(l3);
            *(float4*)(g_ex + (size_t)e_r * 4) = make_float4(e0, e1, e2, e3);
            red_add_v4(&g_z[(size_t)d_r * 4], e0, e1, e2, e3);
        }
    }
}

// ---------------------------------------------------------------------------
// Kernel 3: invert z once per (node, head)
// ---------------------------------------------------------------------------
__global__ void inv_z(int N) {
    int i = blockIdx.x * 256 + threadIdx.x;
    if (i < N * 4) g_z[i] = __frcp_rn(g_z[i]);
}

// ---------------------------------------------------------------------------
// Kernel 4: edge pass 2.  4 lanes/edge; lane t owns dims 4t..4t+3; v4 RED.
// ---------------------------------------------------------------------------
__global__ __launch_bounds__(256)
void edge_aggr(const int* __restrict__ src,
               const int* __restrict__ dst,
               float* __restrict__ out_n,
               int E)
{
    const int tid  = threadIdx.x;
    const int lane = tid & 31;
    const int t    = lane & 3;
    const int le   = (tid >> 5) * 8 + (lane >> 2);
    const long long e = (long long)blockIdx.x * 64 + le;
    if (e >= E) return;

    const int s = src[e];
    const int d = dst[e];

    float4 ex4 = *(const float4*)(g_ex + (size_t)e * 4);
    float4 zi4 = *(const float4*)(g_z  + (size_t)d * 4);
    const float a0 = 0.25f * ex4.x * zi4.x;
    const float a1 = 0.25f * ex4.y * zi4.y;
    const float a2 = 0.25f * ex4.z * zi4.z;
    const float a3 = 0.25f * ex4.w * zi4.w;

    const float* hr = g_hsrc + (size_t)s * 64 + 4 * t;
    float4 v0 = *(const float4*)(hr);
    float4 v1 = *(const float4*)(hr + 16);
    float4 v2 = *(const float4*)(hr + 32);
    float4 v3 = *(const float4*)(hr + 48);

    float m0 = a0 * v0.x + a1 * v1.x + a2 * v2.x + a3 * v3.x;
    float m1 = a0 * v0.y + a1 * v1.y + a2 * v2.y + a3 * v3.y;
    float m2 = a0 * v0.z + a1 * v1.z + a2 * v2.z + a3 * v3.z;
    float m3 = a0 * v0.w + a1 * v1.w + a2 * v2.w + a3 * v3.w;

    red_add_v4(out_n + (size_t)d * 16 + 4 * t, m0, m1, m2, m3);
}

// ---------------------------------------------------------------------------
extern "C" void kernel_launch(void* const* d_in, const int* in_sizes, int n_in,
                              void* d_out, int out_size)
{
    const float* nfeats = (const float*)d_in[0];
    const float* efeats = (const float*)d_in[1];
    const int*   src    = (const int*)  d_in[2];
    const int*   dst    = (const int*)  d_in[3];
    const float* Wni    = (const float*)d_in[4];
    const float* Wnj    = (const float*)d_in[5];
    const float* Wfij   = (const float*)d_in[6];
    const float* Wsrc   = (const float*)d_in[7];
    const float* bsrc   = (const float*)d_in[8];
    const float* attn   = (const float*)d_in[9];
    const float* biase  = (const float*)d_in[10];

    const int N = in_sizes[0] / 128;
    const int E = in_sizes[2];

    float* out_n = (float*)d_out;
    float* out_e = out_n + (size_t)N * 16;

    static int smem_set = 0;
    const int EM_SMEM = (64 * WS * 2 + 8 * WREG + 128) * 4;  // 55808 B
    if (!smem_set) {
        cudaFuncSetAttribute(edge_main,
                             cudaFuncAttributeMaxDynamicSharedMemorySize,
                             EM_SMEM);
        smem_set = 1;
    }

    // launch order: idx 3 (ncu's pick) = edge_main
    zero_kernel<<<(N * 16 + 255) / 256, 256>>>(out_n, N);

    wsplit<<<8, 256>>>(Wfij);

    dim3 g1((N + 255) / 256, 3);
    node_gemm<<<g1, 256>>>(nfeats, Wni, Wnj, Wsrc, bsrc, N);

    edge_main<<<(E + 127) / 128, 256, EM_SMEM>>>(efeats, src, dst,
                                                 attn, biase, out_e, E);

    inv_z<<<(N * 4 + 255) / 256, 256>>>(N);

    edge_aggr<<<(E + 63) / 64, 256>>>(src, dst, out_n, E);
}